// round 3
// baseline (speedup 1.0000x reference)
#include <cuda_runtime.h>
#include <cstdint>

// ---------------- problem constants ----------------
#define Bc   4
#define Nc_  1024
#define Dc   512
#define Hc   8
#define DHc  64
#define TCc  512
#define ABc  16
#define NEGc 1e6f
#define EPSc 1e-5f

// ---------------- device scratch (no allocs allowed) ----------------
__device__ float g_st[Bc * 2 * Dc];                         // FiLM scale/shift  [B][1024]
__device__ float g_xn[Bc * Nc_ * Dc];                       // normed+FiLM input (8MB)
__device__ float g_q[Bc * Hc * Nc_ * DHc];                  // q head-major (8MB)
__device__ float g_k[Bc * Hc * Nc_ * DHc];                  // k head-major (8MB)
__device__ float g_v[Bc * Hc * Nc_ * DHc];                  // v head-major (8MB)
__device__ float g_attn[Bc * Nc_ * Hc * DHc];               // attention out [B,N,H*DH] (8MB)
__device__ float g_bias[(size_t)Bc * Hc * Nc_ * Nc_];       // projected bias+mask (128MB)

// ---------------- helpers ----------------
__device__ __forceinline__ unsigned f2tf(float x) {
    unsigned u;
    asm("cvt.rna.tf32.f32 %0, %1;" : "=r"(u) : "f"(x));
    return u;
}

__device__ __forceinline__ void mma8(float* c, const unsigned* a, const unsigned* b) {
    asm volatile(
        "mma.sync.aligned.m16n8k8.row.col.f32.tf32.tf32.f32 "
        "{%0,%1,%2,%3},{%4,%5,%6,%7},{%8,%9},{%0,%1,%2,%3};\n"
        : "+f"(c[0]), "+f"(c[1]), "+f"(c[2]), "+f"(c[3])
        : "r"(a[0]), "r"(a[1]), "r"(a[2]), "r"(a[3]), "r"(b[0]), "r"(b[1]));
}

// ---------------- kernel 1: FiLM  t = silu(time) @ Wt^T + bt ----------------
// one warp per output element j (4096 outputs)
__global__ void film_kernel(const float* __restrict__ time,
                            const float* __restrict__ Wt,
                            const float* __restrict__ bt) {
    int warp = (blockIdx.x * blockDim.x + threadIdx.x) >> 5;
    int lane = threadIdx.x & 31;
    if (warp >= Bc * 2 * Dc) return;
    int b = warp >> 10;
    int j = warp & 1023;
    const float* t = time + b * TCc;
    const float* w = Wt + (size_t)j * TCc;
    float s = 0.f;
    #pragma unroll 4
    for (int c = lane; c < TCc; c += 32) {
        float x = t[c];
        float sl = x / (1.f + expf(-x));
        s += sl * w[c];
    }
    #pragma unroll
    for (int o = 16; o; o >>= 1) s += __shfl_xor_sync(0xffffffffu, s, o);
    if (lane == 0) g_st[b * 1024 + j] = s + bt[j];
}

// ---------------- kernel 2: LayerNorm + FiLM + seq mask ----------------
__global__ void ln_film_kernel(const float* __restrict__ x,
                               const float* __restrict__ gamma,
                               const float* __restrict__ seq_mask) {
    int row = blockIdx.x;          // 0..4095  (b*1024+n)
    int b   = row >> 10;
    int tid = threadIdx.x;         // 128 threads
    const float* xr = x + (size_t)row * Dc;
    float v[4];
    float s = 0.f, sq = 0.f;
    #pragma unroll
    for (int k = 0; k < 4; k++) {
        v[k] = xr[tid + 128 * k];
        s += v[k];
        sq += v[k] * v[k];
    }
    __shared__ float red[8];
    #pragma unroll
    for (int o = 16; o; o >>= 1) {
        s  += __shfl_xor_sync(0xffffffffu, s, o);
        sq += __shfl_xor_sync(0xffffffffu, sq, o);
    }
    int w = tid >> 5;
    if ((tid & 31) == 0) { red[w] = s; red[4 + w] = sq; }
    __syncthreads();
    s  = red[0] + red[1] + red[2] + red[3];
    sq = red[4] + red[5] + red[6] + red[7];
    float mu  = s * (1.f / 512.f);
    float var = sq * (1.f / 512.f) - mu * mu;
    float inv = rsqrtf(var + EPSc);
    float mask = seq_mask[row];
    float* o = g_xn + (size_t)row * Dc;
    #pragma unroll
    for (int k = 0; k < 4; k++) {
        int d = tid + 128 * k;
        float scale = g_st[b * 1024 + d];
        float shift = g_st[b * 1024 + 512 + d];
        float xn = (v[k] - mu) * inv * gamma[d];
        xn = xn * (scale + 1.f) + shift;
        o[d] = xn * mask;
    }
}

// ---------------- kernel 3/4/7: tf32 GEMM  C[M,NC] = A[M,512] * B[NC,512]^T ----------------
// MODE 0: A=g_xn,  out = q * DH^-0.5 -> g_q head-major
// MODE 1: A=x,     out cols<512 -> g_k head-major, cols>=512 -> g_v head-major
// MODE 2: A=g_attn,out -> d_out * seq_mask
template <int MODE>
__global__ void __launch_bounds__(128)
gemm_kernel(const float* __restrict__ Ain,
            const float* __restrict__ Bw,
            float* __restrict__ Out,
            const float* __restrict__ seq_mask) {
    __shared__ __align__(16) unsigned As[64 * 36];
    __shared__ __align__(16) unsigned Bs[64 * 36];
    const float* A = (MODE == 0) ? g_xn : (MODE == 2 ? g_attn : Ain);

    const int m0 = blockIdx.y * 64;
    const int n0 = blockIdx.x * 64;
    const int tid = threadIdx.x;
    const int w = tid >> 5, lane = tid & 31;
    const int wm = w & 1, wn = w >> 1;
    const int r = lane >> 2, q = lane & 3;

    float C[2][4][4];
    #pragma unroll
    for (int mb = 0; mb < 2; mb++)
        #pragma unroll
        for (int nb = 0; nb < 4; nb++)
            #pragma unroll
            for (int e = 0; e < 4; e++) C[mb][nb][e] = 0.f;

    for (int kc = 0; kc < 512; kc += 32) {
        #pragma unroll
        for (int l = 0; l < 4; l++) {
            int f = l * 128 + tid;            // 0..511 float4 slots
            int row = f >> 3, c4 = (f & 7) * 4;
            float4 va = *(const float4*)&A[(size_t)(m0 + row) * 512 + kc + c4];
            *(uint4*)&As[row * 36 + c4] =
                make_uint4(f2tf(va.x), f2tf(va.y), f2tf(va.z), f2tf(va.w));
            float4 vb = *(const float4*)&Bw[(size_t)(n0 + row) * 512 + kc + c4];
            *(uint4*)&Bs[row * 36 + c4] =
                make_uint4(f2tf(vb.x), f2tf(vb.y), f2tf(vb.z), f2tf(vb.w));
        }
        __syncthreads();
        #pragma unroll
        for (int ks = 0; ks < 4; ks++) {
            unsigned a[2][4], b[4][2];
            #pragma unroll
            for (int mb = 0; mb < 2; mb++) {
                int rr = wm * 32 + mb * 16 + r;
                a[mb][0] = As[rr * 36 + ks * 8 + q];
                a[mb][1] = As[(rr + 8) * 36 + ks * 8 + q];
                a[mb][2] = As[rr * 36 + ks * 8 + q + 4];
                a[mb][3] = As[(rr + 8) * 36 + ks * 8 + q + 4];
            }
            #pragma unroll
            for (int nb = 0; nb < 4; nb++) {
                int nr = wn * 32 + nb * 8 + r;
                b[nb][0] = Bs[nr * 36 + ks * 8 + q];
                b[nb][1] = Bs[nr * 36 + ks * 8 + q + 4];
            }
            #pragma unroll
            for (int mb = 0; mb < 2; mb++)
                #pragma unroll
                for (int nb = 0; nb < 4; nb++)
                    mma8(C[mb][nb], a[mb], b[nb]);
        }
        __syncthreads();
    }

    // epilogue
    #pragma unroll
    for (int mb = 0; mb < 2; mb++) {
        #pragma unroll
        for (int nb = 0; nb < 4; nb++) {
            #pragma unroll
            for (int e = 0; e < 4; e += 2) {
                int row = m0 + wm * 32 + mb * 16 + r + (e ? 8 : 0);
                int col = n0 + wn * 32 + nb * 8 + 2 * q;
                float2 val = make_float2(C[mb][nb][e], C[mb][nb][e + 1]);
                if (MODE == 0) {
                    val.x *= 0.125f; val.y *= 0.125f;     // DH^-0.5
                    int bb_ = row >> 10, n = row & 1023;
                    int h = col >> 6, dh = col & 63;
                    *(float2*)&g_q[(((size_t)(bb_ * 8 + h)) << 16) + (n << 6) + dh] = val;
                } else if (MODE == 1) {
                    int bb_ = row >> 10, n = row & 1023;
                    if (col < 512) {
                        int h = col >> 6, dh = col & 63;
                        *(float2*)&g_k[(((size_t)(bb_ * 8 + h)) << 16) + (n << 6) + dh] = val;
                    } else {
                        int c2 = col - 512;
                        int h = c2 >> 6, dh = c2 & 63;
                        *(float2*)&g_v[(((size_t)(bb_ * 8 + h)) << 16) + (n << 6) + dh] = val;
                    }
                } else {
                    float mk = seq_mask[row];
                    val.x *= mk; val.y *= mk;
                    *(float2*)&Out[(size_t)row * 512 + col] = val;
                }
            }
        }
    }
}

// ---------------- kernel 5: bias projection + mask fold ----------------
// g_bias[b,h,i,j] = sum_a Wb[h,a]*ab[b,a,i,j] + bb[h] - (1-mi*mj)*NEG
__global__ void bias_kernel(const float* __restrict__ ab,
                            const float* __restrict__ Wb,
                            const float* __restrict__ bb,
                            const float* __restrict__ seq_mask) {
    __shared__ float wbs[136];
    int tid = threadIdx.x;
    if (tid < 128) wbs[tid] = Wb[tid];
    if (tid < 8)   wbs[128 + tid] = bb[tid];
    __syncthreads();

    long idx = (long)blockIdx.x * 256 + tid;   // 1,048,576 threads total
    int j4 = (int)(idx & 255);
    int i  = (int)((idx >> 8) & 1023);
    int b  = (int)(idx >> 18);
    int j0 = j4 * 4;

    const float* base = ab + (((long)(b * 16)) << 20) + ((long)i << 10) + j0;
    float4 acc[8];
    #pragma unroll
    for (int h = 0; h < 8; h++) acc[h] = make_float4(0.f, 0.f, 0.f, 0.f);

    #pragma unroll
    for (int a = 0; a < 16; a++) {
        float4 v = *(const float4*)(base + ((long)a << 20));
        #pragma unroll
        for (int h = 0; h < 8; h++) {
            float wv = wbs[h * 16 + a];
            acc[h].x += wv * v.x;
            acc[h].y += wv * v.y;
            acc[h].z += wv * v.z;
            acc[h].w += wv * v.w;
        }
    }
    float mi = seq_mask[b * 1024 + i];
    float4 mj = *(const float4*)&seq_mask[b * 1024 + j0];
    float4 pen;
    pen.x = -(1.f - mi * mj.x) * NEGc;
    pen.y = -(1.f - mi * mj.y) * NEGc;
    pen.z = -(1.f - mi * mj.z) * NEGc;
    pen.w = -(1.f - mi * mj.w) * NEGc;
    #pragma unroll
    for (int h = 0; h < 8; h++) {
        float bbv = wbs[128 + h];
        float4 o;
        o.x = acc[h].x + bbv + pen.x;
        o.y = acc[h].y + bbv + pen.y;
        o.z = acc[h].z + bbv + pen.z;
        o.w = acc[h].w + bbv + pen.w;
        *(float4*)&g_bias[(((long)(b * 8 + h)) << 20) + ((long)i << 10) + j0] = o;
    }
}

// ---------------- kernel 6: flash attention per (b,h, 64-row q tile) ----------------
__global__ void __launch_bounds__(128) attn_kernel() {
    __shared__ __align__(16) unsigned Ksm[64 * 68];   // reused as P stage after S compute
    __shared__ __align__(16) unsigned Vsm[64 * 72];

    const int i0 = blockIdx.x * 64;
    const int h  = blockIdx.y;
    const int b  = blockIdx.z;
    const int bh = b * 8 + h;
    const int tid = threadIdx.x, w = tid >> 5, lane = tid & 31;
    const int r = lane >> 2, q = lane & 3;

    const float* Q  = g_q + ((size_t)bh << 16);
    const float* Kg = g_k + ((size_t)bh << 16);
    const float* Vg = g_v + ((size_t)bh << 16);
    const float* Bb = g_bias + ((long)bh << 20);

    const int rowA = i0 + w * 16 + r;     // this thread's first q-row

    unsigned qf[8][4];
    #pragma unroll
    for (int ks = 0; ks < 8; ks++) {
        qf[ks][0] = f2tf(Q[(size_t)rowA * 64 + ks * 8 + q]);
        qf[ks][1] = f2tf(Q[(size_t)(rowA + 8) * 64 + ks * 8 + q]);
        qf[ks][2] = f2tf(Q[(size_t)rowA * 64 + ks * 8 + q + 4]);
        qf[ks][3] = f2tf(Q[(size_t)(rowA + 8) * 64 + ks * 8 + q + 4]);
    }

    float O[8][4];
    #pragma unroll
    for (int nb = 0; nb < 8; nb++)
        #pragma unroll
        for (int e = 0; e < 4; e++) O[nb][e] = 0.f;
    float mrun0 = -1e30f, mrun1 = -1e30f;
    float lrun0 = 0.f, lrun1 = 0.f;

    unsigned* Psm = Ksm + w * 16 * 68;

    for (int jt = 0; jt < 16; jt++) {
        int j0 = jt * 64;
        // cooperative K/V tile load (fp32 -> tf32)
        #pragma unroll
        for (int l = 0; l < 8; l++) {
            int f = l * 128 + tid;                // 0..1023 float4 slots
            int row = f >> 4, c4 = (f & 15) * 4;
            float4 kv = *(const float4*)&Kg[(size_t)(j0 + row) * 64 + c4];
            *(uint4*)&Ksm[row * 68 + c4] =
                make_uint4(f2tf(kv.x), f2tf(kv.y), f2tf(kv.z), f2tf(kv.w));
            float4 vv = *(const float4*)&Vg[(size_t)(j0 + row) * 64 + c4];
            *(uint4*)&Vsm[row * 72 + c4] =
                make_uint4(f2tf(vv.x), f2tf(vv.y), f2tf(vv.z), f2tf(vv.w));
        }
        __syncthreads();

        // S accumulators pre-loaded with bias (+mask penalty already folded)
        float S[8][4];
        #pragma unroll
        for (int nb = 0; nb < 8; nb++) {
            int col = j0 + nb * 8 + 2 * q;
            float2 b01 = *(const float2*)&Bb[(long)rowA * 1024 + col];
            float2 b23 = *(const float2*)&Bb[(long)(rowA + 8) * 1024 + col];
            S[nb][0] = b01.x; S[nb][1] = b01.y;
            S[nb][2] = b23.x; S[nb][3] = b23.y;
        }
        // S += Q K^T
        #pragma unroll
        for (int ks = 0; ks < 8; ks++) {
            #pragma unroll
            for (int nb = 0; nb < 8; nb++) {
                unsigned bf[2];
                bf[0] = Ksm[(nb * 8 + r) * 68 + ks * 8 + q];
                bf[1] = Ksm[(nb * 8 + r) * 68 + ks * 8 + q + 4];
                mma8(S[nb], qf[ks], bf);
            }
        }

        // online softmax over the two rows this thread owns
        float mx0 = -1e30f, mx1 = -1e30f;
        #pragma unroll
        for (int nb = 0; nb < 8; nb++) {
            mx0 = fmaxf(mx0, fmaxf(S[nb][0], S[nb][1]));
            mx1 = fmaxf(mx1, fmaxf(S[nb][2], S[nb][3]));
        }
        mx0 = fmaxf(mx0, __shfl_xor_sync(0xffffffffu, mx0, 1));
        mx0 = fmaxf(mx0, __shfl_xor_sync(0xffffffffu, mx0, 2));
        mx1 = fmaxf(mx1, __shfl_xor_sync(0xffffffffu, mx1, 1));
        mx1 = fmaxf(mx1, __shfl_xor_sync(0xffffffffu, mx1, 2));
        float mn0 = fmaxf(mrun0, mx0), mn1 = fmaxf(mrun1, mx1);
        float al0 = __expf(mrun0 - mn0), al1 = __expf(mrun1 - mn1);
        float rs0 = 0.f, rs1 = 0.f;
        #pragma unroll
        for (int nb = 0; nb < 8; nb++) {
            S[nb][0] = __expf(S[nb][0] - mn0);
            S[nb][1] = __expf(S[nb][1] - mn0);
            S[nb][2] = __expf(S[nb][2] - mn1);
            S[nb][3] = __expf(S[nb][3] - mn1);
            rs0 += S[nb][0] + S[nb][1];
            rs1 += S[nb][2] + S[nb][3];
        }
        rs0 += __shfl_xor_sync(0xffffffffu, rs0, 1);
        rs0 += __shfl_xor_sync(0xffffffffu, rs0, 2);
        rs1 += __shfl_xor_sync(0xffffffffu, rs1, 1);
        rs1 += __shfl_xor_sync(0xffffffffu, rs1, 2);
        lrun0 = lrun0 * al0 + rs0;
        lrun1 = lrun1 * al1 + rs1;
        mrun0 = mn0; mrun1 = mn1;
        #pragma unroll
        for (int nb = 0; nb < 8; nb++) {
            O[nb][0] *= al0; O[nb][1] *= al0;
            O[nb][2] *= al1; O[nb][3] *= al1;
        }

        __syncthreads();   // everyone done reading Ksm before we overwrite with P
        #pragma unroll
        for (int nb = 0; nb < 8; nb++) {
            Psm[r * 68 + nb * 8 + 2 * q]           = f2tf(S[nb][0]);
            Psm[r * 68 + nb * 8 + 2 * q + 1]       = f2tf(S[nb][1]);
            Psm[(r + 8) * 68 + nb * 8 + 2 * q]     = f2tf(S[nb][2]);
            Psm[(r + 8) * 68 + nb * 8 + 2 * q + 1] = f2tf(S[nb][3]);
        }
        __syncwarp();

        // O += P V
        #pragma unroll
        for (int ks = 0; ks < 8; ks++) {
            unsigned a[4];
            a[0] = Psm[r * 68 + ks * 8 + q];
            a[1] = Psm[(r + 8) * 68 + ks * 8 + q];
            a[2] = Psm[r * 68 + ks * 8 + q + 4];
            a[3] = Psm[(r + 8) * 68 + ks * 8 + q + 4];
            #pragma unroll
            for (int nb = 0; nb < 8; nb++) {
                unsigned bf[2];
                bf[0] = Vsm[(ks * 8 + q) * 72 + nb * 8 + r];
                bf[1] = Vsm[(ks * 8 + q + 4) * 72 + nb * 8 + r];
                mma8(O[nb], a, bf);
            }
        }
        __syncthreads();   // done with Vsm/Psm before next tile load
    }

    float inv0 = 1.f / lrun0;
    float inv1 = 1.f / lrun1;
    float* Og = g_attn + ((size_t)b << 10) * 512;
    #pragma unroll
    for (int nb = 0; nb < 8; nb++) {
        int col = h * 64 + nb * 8 + 2 * q;
        *(float2*)&Og[(size_t)rowA * 512 + col] =
            make_float2(O[nb][0] * inv0, O[nb][1] * inv0);
        *(float2*)&Og[(size_t)(rowA + 8) * 512 + col] =
            make_float2(O[nb][2] * inv1, O[nb][3] * inv1);
    }
}

// ---------------- launch ----------------
extern "C" void kernel_launch(void* const* d_in, const int* in_sizes, int n_in,
                              void* d_out, int out_size) {
    const float* x        = (const float*)d_in[0];
    const float* time     = (const float*)d_in[1];
    const float* ab       = (const float*)d_in[2];
    const float* seq_mask = (const float*)d_in[3];
    const float* gamma    = (const float*)d_in[4];
    const float* Wt       = (const float*)d_in[5];
    const float* bt       = (const float*)d_in[6];
    const float* Wq       = (const float*)d_in[7];
    const float* Wkv      = (const float*)d_in[8];
    const float* Wo       = (const float*)d_in[9];
    const float* Wb       = (const float*)d_in[10];
    const float* bb       = (const float*)d_in[11];
    float* out = (float*)d_out;

    film_kernel<<<512, 256>>>(time, Wt, bt);
    ln_film_kernel<<<4096, 128>>>(x, gamma, seq_mask);
    gemm_kernel<0><<<dim3(8, 64), 128>>>(nullptr, Wq, nullptr, seq_mask);
    gemm_kernel<1><<<dim3(16, 64), 128>>>(x, Wkv, nullptr, seq_mask);
    bias_kernel<<<4096, 256>>>(ab, Wb, bb, seq_mask);
    attn_kernel<<<dim3(16, 8, 4), 128>>>();
    gemm_kernel<2><<<dim3(8, 64), 128>>>(nullptr, Wo, out, seq_mask);
}

// round 4
// speedup vs baseline: 1.1440x; 1.1440x over previous
#include <cuda_runtime.h>
#include <cuda_fp16.h>
#include <cstdint>

// ---------------- problem constants ----------------
#define Bc   4
#define Nc_  1024
#define Dc   512
#define Hc   8
#define DHc  64
#define TCc  512
#define ABc  16
#define NEGc 1e6f
#define EPSc 1e-5f

// ---------------- device scratch (no allocs allowed) ----------------
__device__ float g_st[Bc * 2 * Dc];                         // FiLM scale/shift  [B][1024]
__device__ float g_xn[Bc * Nc_ * Dc];                       // normed+FiLM input (8MB)
__device__ float g_q[Bc * Hc * Nc_ * DHc];                  // q head-major (8MB)
__device__ float g_k[Bc * Hc * Nc_ * DHc];                  // k head-major (8MB)
__device__ float g_v[Bc * Hc * Nc_ * DHc];                  // v head-major (8MB)
__device__ float g_attn[Bc * Nc_ * Hc * DHc];               // attention out [B,N,H*DH] (8MB)
__device__ __half g_bias_h[(size_t)Bc * Hc * Nc_ * Nc_];    // projected bias+mask fp16 (64MB)

// ---------------- helpers ----------------
__device__ __forceinline__ unsigned f2tf(float x) {
    unsigned u;
    asm("cvt.rna.tf32.f32 %0, %1;" : "=r"(u) : "f"(x));
    return u;
}

__device__ __forceinline__ void mma8(float* c, const unsigned* a, const unsigned* b) {
    asm volatile(
        "mma.sync.aligned.m16n8k8.row.col.f32.tf32.tf32.f32 "
        "{%0,%1,%2,%3},{%4,%5,%6,%7},{%8,%9},{%0,%1,%2,%3};\n"
        : "+f"(c[0]), "+f"(c[1]), "+f"(c[2]), "+f"(c[3])
        : "r"(a[0]), "r"(a[1]), "r"(a[2]), "r"(a[3]), "r"(b[0]), "r"(b[1]));
}

// ---------------- kernel 1: FiLM  t = silu(time) @ Wt^T + bt ----------------
__global__ void film_kernel(const float* __restrict__ time,
                            const float* __restrict__ Wt,
                            const float* __restrict__ bt) {
    int warp = (blockIdx.x * blockDim.x + threadIdx.x) >> 5;
    int lane = threadIdx.x & 31;
    if (warp >= Bc * 2 * Dc) return;
    int b = warp >> 10;
    int j = warp & 1023;
    const float* t = time + b * TCc;
    const float* w = Wt + (size_t)j * TCc;
    float s = 0.f;
    #pragma unroll 4
    for (int c = lane; c < TCc; c += 32) {
        float x = t[c];
        float sl = x / (1.f + expf(-x));
        s += sl * w[c];
    }
    #pragma unroll
    for (int o = 16; o; o >>= 1) s += __shfl_xor_sync(0xffffffffu, s, o);
    if (lane == 0) g_st[b * 1024 + j] = s + bt[j];
}

// ---------------- kernel 2: LayerNorm + FiLM + seq mask ----------------
__global__ void ln_film_kernel(const float* __restrict__ x,
                               const float* __restrict__ gamma,
                               const float* __restrict__ seq_mask) {
    int row = blockIdx.x;          // 0..4095  (b*1024+n)
    int b   = row >> 10;
    int tid = threadIdx.x;         // 128 threads
    const float* xr = x + (size_t)row * Dc;
    float v[4];
    float s = 0.f, sq = 0.f;
    #pragma unroll
    for (int k = 0; k < 4; k++) {
        v[k] = xr[tid + 128 * k];
        s += v[k];
        sq += v[k] * v[k];
    }
    __shared__ float red[8];
    #pragma unroll
    for (int o = 16; o; o >>= 1) {
        s  += __shfl_xor_sync(0xffffffffu, s, o);
        sq += __shfl_xor_sync(0xffffffffu, sq, o);
    }
    int w = tid >> 5;
    if ((tid & 31) == 0) { red[w] = s; red[4 + w] = sq; }
    __syncthreads();
    s  = red[0] + red[1] + red[2] + red[3];
    sq = red[4] + red[5] + red[6] + red[7];
    float mu  = s * (1.f / 512.f);
    float var = sq * (1.f / 512.f) - mu * mu;
    float inv = rsqrtf(var + EPSc);
    float mask = seq_mask[row];
    float* o = g_xn + (size_t)row * Dc;
    #pragma unroll
    for (int k = 0; k < 4; k++) {
        int d = tid + 128 * k;
        float scale = g_st[b * 1024 + d];
        float shift = g_st[b * 1024 + 512 + d];
        float xn = (v[k] - mu) * inv * gamma[d];
        xn = xn * (scale + 1.f) + shift;
        o[d] = xn * mask;
    }
}

// ---------------- tf32 GEMM v2: 128x64 tile, 256 threads, pipelined ----------------
// C[M,NC] = A[M,512] * B[NC,512]^T
// MODE 0: A=g_xn,  out = q * DH^-0.5 -> g_q head-major
// MODE 1: A=x,     out cols<512 -> g_k head-major, cols>=512 -> g_v head-major
// MODE 2: A=g_attn,out -> d_out * seq_mask
template <int MODE>
__global__ void __launch_bounds__(256)
gemm_kernel(const float* __restrict__ Ain,
            const float* __restrict__ Bw,
            float* __restrict__ Out,
            const float* __restrict__ seq_mask) {
    __shared__ __align__(16) unsigned As[128 * 36];
    __shared__ __align__(16) unsigned Bs[64 * 36];
    const float* A = (MODE == 0) ? g_xn : (MODE == 2 ? g_attn : Ain);

    const int m0 = blockIdx.y * 128;
    const int n0 = blockIdx.x * 64;
    const int tid = threadIdx.x;
    const int w = tid >> 5, lane = tid & 31;
    const int wm = w & 3, wn = w >> 2;   // 4 warps along M (32 rows), 2 along N (32 cols)
    const int r = lane >> 2, q = lane & 3;

    float C[2][4][4];
    #pragma unroll
    for (int mb = 0; mb < 2; mb++)
        #pragma unroll
        for (int nb = 0; nb < 4; nb++)
            #pragma unroll
            for (int e = 0; e < 4; e++) C[mb][nb][e] = 0.f;

    float4 ra[4], rb[2];
    // prologue: load chunk 0
    #pragma unroll
    for (int l = 0; l < 4; l++) {
        int f = l * 256 + tid;
        int row = f >> 3, c4 = (f & 7) * 4;
        ra[l] = *(const float4*)&A[(size_t)(m0 + row) * 512 + c4];
    }
    #pragma unroll
    for (int l = 0; l < 2; l++) {
        int f = l * 256 + tid;
        int row = f >> 3, c4 = (f & 7) * 4;
        rb[l] = *(const float4*)&Bw[(size_t)(n0 + row) * 512 + c4];
    }

    for (int kc = 0; kc < 512; kc += 32) {
        // stage current chunk to smem (tf32 conversion at store)
        #pragma unroll
        for (int l = 0; l < 4; l++) {
            int f = l * 256 + tid;
            int row = f >> 3, c4 = (f & 7) * 4;
            *(uint4*)&As[row * 36 + c4] =
                make_uint4(f2tf(ra[l].x), f2tf(ra[l].y), f2tf(ra[l].z), f2tf(ra[l].w));
        }
        #pragma unroll
        for (int l = 0; l < 2; l++) {
            int f = l * 256 + tid;
            int row = f >> 3, c4 = (f & 7) * 4;
            *(uint4*)&Bs[row * 36 + c4] =
                make_uint4(f2tf(rb[l].x), f2tf(rb[l].y), f2tf(rb[l].z), f2tf(rb[l].w));
        }
        __syncthreads();

        // prefetch next chunk (hidden behind the MMA work below)
        if (kc + 32 < 512) {
            #pragma unroll
            for (int l = 0; l < 4; l++) {
                int f = l * 256 + tid;
                int row = f >> 3, c4 = (f & 7) * 4;
                ra[l] = *(const float4*)&A[(size_t)(m0 + row) * 512 + kc + 32 + c4];
            }
            #pragma unroll
            for (int l = 0; l < 2; l++) {
                int f = l * 256 + tid;
                int row = f >> 3, c4 = (f & 7) * 4;
                rb[l] = *(const float4*)&Bw[(size_t)(n0 + row) * 512 + kc + 32 + c4];
            }
        }

        #pragma unroll
        for (int ks = 0; ks < 4; ks++) {
            unsigned a[2][4], b[4][2];
            #pragma unroll
            for (int mb = 0; mb < 2; mb++) {
                int rr = wm * 32 + mb * 16 + r;
                a[mb][0] = As[rr * 36 + ks * 8 + q];
                a[mb][1] = As[(rr + 8) * 36 + ks * 8 + q];
                a[mb][2] = As[rr * 36 + ks * 8 + q + 4];
                a[mb][3] = As[(rr + 8) * 36 + ks * 8 + q + 4];
            }
            #pragma unroll
            for (int nb = 0; nb < 4; nb++) {
                int nr = wn * 32 + nb * 8 + r;
                b[nb][0] = Bs[nr * 36 + ks * 8 + q];
                b[nb][1] = Bs[nr * 36 + ks * 8 + q + 4];
            }
            #pragma unroll
            for (int mb = 0; mb < 2; mb++)
                #pragma unroll
                for (int nb = 0; nb < 4; nb++)
                    mma8(C[mb][nb], a[mb], b[nb]);
        }
        __syncthreads();
    }

    // epilogue
    #pragma unroll
    for (int mb = 0; mb < 2; mb++) {
        #pragma unroll
        for (int nb = 0; nb < 4; nb++) {
            #pragma unroll
            for (int e = 0; e < 4; e += 2) {
                int row = m0 + wm * 32 + mb * 16 + r + (e ? 8 : 0);
                int col = n0 + wn * 32 + nb * 8 + 2 * q;
                float2 val = make_float2(C[mb][nb][e], C[mb][nb][e + 1]);
                if (MODE == 0) {
                    val.x *= 0.125f; val.y *= 0.125f;     // DH^-0.5
                    int bb_ = row >> 10, n = row & 1023;
                    int h = col >> 6, dh = col & 63;
                    *(float2*)&g_q[(((size_t)(bb_ * 8 + h)) << 16) + (n << 6) + dh] = val;
                } else if (MODE == 1) {
                    int bb_ = row >> 10, n = row & 1023;
                    if (col < 512) {
                        int h = col >> 6, dh = col & 63;
                        *(float2*)&g_k[(((size_t)(bb_ * 8 + h)) << 16) + (n << 6) + dh] = val;
                    } else {
                        int c2 = col - 512;
                        int h = c2 >> 6, dh = c2 & 63;
                        *(float2*)&g_v[(((size_t)(bb_ * 8 + h)) << 16) + (n << 6) + dh] = val;
                    }
                } else {
                    float mk = seq_mask[row];
                    val.x *= mk; val.y *= mk;
                    *(float2*)&Out[(size_t)row * 512 + col] = val;
                }
            }
        }
    }
}

// ---------------- bias projection + mask fold -> fp16 ----------------
// g_bias_h[b,h,i,j] = sum_a Wb[h,a]*ab[b,a,i,j] + bb[h] - (1-mi*mj)*NEG (clamped for fp16)
__global__ void bias_kernel(const float* __restrict__ ab,
                            const float* __restrict__ Wb,
                            const float* __restrict__ bb,
                            const float* __restrict__ seq_mask) {
    __shared__ float wbs[136];
    int tid = threadIdx.x;
    if (tid < 128) wbs[tid] = Wb[tid];
    if (tid < 8)   wbs[128 + tid] = bb[tid];
    __syncthreads();

    long idx = (long)blockIdx.x * 256 + tid;   // 1,048,576 threads total
    int j4 = (int)(idx & 255);
    int i  = (int)((idx >> 8) & 1023);
    int b  = (int)(idx >> 18);
    int j0 = j4 * 4;

    const float* base = ab + (((long)(b * 16)) << 20) + ((long)i << 10) + j0;
    float4 acc[8];
    #pragma unroll
    for (int h = 0; h < 8; h++) acc[h] = make_float4(0.f, 0.f, 0.f, 0.f);

    #pragma unroll
    for (int a = 0; a < 16; a++) {
        float4 v = *(const float4*)(base + ((long)a << 20));
        #pragma unroll
        for (int h = 0; h < 8; h++) {
            float wv = wbs[h * 16 + a];
            acc[h].x += wv * v.x;
            acc[h].y += wv * v.y;
            acc[h].z += wv * v.z;
            acc[h].w += wv * v.w;
        }
    }
    float mi = seq_mask[b * 1024 + i];
    float4 mj = *(const float4*)&seq_mask[b * 1024 + j0];
    float4 pen;
    pen.x = -(1.f - mi * mj.x) * NEGc;
    pen.y = -(1.f - mi * mj.y) * NEGc;
    pen.z = -(1.f - mi * mj.z) * NEGc;
    pen.w = -(1.f - mi * mj.w) * NEGc;
    #pragma unroll
    for (int h = 0; h < 8; h++) {
        float bbv = wbs[128 + h];
        float4 o;
        // clamp so masked entries stay finite in fp16 (exp() underflows to 0 either way)
        o.x = fmaxf(acc[h].x + bbv + pen.x, -60000.f);
        o.y = fmaxf(acc[h].y + bbv + pen.y, -60000.f);
        o.z = fmaxf(acc[h].z + bbv + pen.z, -60000.f);
        o.w = fmaxf(acc[h].w + bbv + pen.w, -60000.f);
        __half* dst = &g_bias_h[(((long)(b * 8 + h)) << 20) + ((long)i << 10) + j0];
        *(__half2*)&dst[0] = __floats2half2_rn(o.x, o.y);
        *(__half2*)&dst[2] = __floats2half2_rn(o.z, o.w);
    }
}

// ---------------- flash attention per (b,h, 64-row q tile) ----------------
__global__ void __launch_bounds__(128) attn_kernel() {
    __shared__ __align__(16) unsigned Ksm[64 * 68];   // reused as P stage after S compute
    __shared__ __align__(16) unsigned Vsm[64 * 72];

    const int i0 = blockIdx.x * 64;
    const int h  = blockIdx.y;
    const int b  = blockIdx.z;
    const int bh = b * 8 + h;
    const int tid = threadIdx.x, w = tid >> 5, lane = tid & 31;
    const int r = lane >> 2, q = lane & 3;

    const float* Q  = g_q + ((size_t)bh << 16);
    const float* Kg = g_k + ((size_t)bh << 16);
    const float* Vg = g_v + ((size_t)bh << 16);
    const __half* Bb = g_bias_h + ((long)bh << 20);

    const int rowA = i0 + w * 16 + r;     // this thread's first q-row

    unsigned qf[8][4];
    #pragma unroll
    for (int ks = 0; ks < 8; ks++) {
        qf[ks][0] = f2tf(Q[(size_t)rowA * 64 + ks * 8 + q]);
        qf[ks][1] = f2tf(Q[(size_t)(rowA + 8) * 64 + ks * 8 + q]);
        qf[ks][2] = f2tf(Q[(size_t)rowA * 64 + ks * 8 + q + 4]);
        qf[ks][3] = f2tf(Q[(size_t)(rowA + 8) * 64 + ks * 8 + q + 4]);
    }

    float O[8][4];
    #pragma unroll
    for (int nb = 0; nb < 8; nb++)
        #pragma unroll
        for (int e = 0; e < 4; e++) O[nb][e] = 0.f;
    float mrun0 = -1e30f, mrun1 = -1e30f;
    float lrun0 = 0.f, lrun1 = 0.f;

    unsigned* Psm = Ksm + w * 16 * 68;

    for (int jt = 0; jt < 16; jt++) {
        int j0 = jt * 64;
        // cooperative K/V tile load (fp32 -> tf32)
        #pragma unroll
        for (int l = 0; l < 8; l++) {
            int f = l * 128 + tid;                // 0..1023 float4 slots
            int row = f >> 4, c4 = (f & 15) * 4;
            float4 kv = *(const float4*)&Kg[(size_t)(j0 + row) * 64 + c4];
            *(uint4*)&Ksm[row * 68 + c4] =
                make_uint4(f2tf(kv.x), f2tf(kv.y), f2tf(kv.z), f2tf(kv.w));
            float4 vv = *(const float4*)&Vg[(size_t)(j0 + row) * 64 + c4];
            *(uint4*)&Vsm[row * 72 + c4] =
                make_uint4(f2tf(vv.x), f2tf(vv.y), f2tf(vv.z), f2tf(vv.w));
        }
        __syncthreads();

        // S accumulators pre-loaded with bias (+mask penalty already folded)
        float S[8][4];
        #pragma unroll
        for (int nb = 0; nb < 8; nb++) {
            int col = j0 + nb * 8 + 2 * q;
            float2 b01 = __half22float2(*(const __half2*)&Bb[(long)rowA * 1024 + col]);
            float2 b23 = __half22float2(*(const __half2*)&Bb[(long)(rowA + 8) * 1024 + col]);
            S[nb][0] = b01.x; S[nb][1] = b01.y;
            S[nb][2] = b23.x; S[nb][3] = b23.y;
        }
        // S += Q K^T
        #pragma unroll
        for (int ks = 0; ks < 8; ks++) {
            #pragma unroll
            for (int nb = 0; nb < 8; nb++) {
                unsigned bf[2];
                bf[0] = Ksm[(nb * 8 + r) * 68 + ks * 8 + q];
                bf[1] = Ksm[(nb * 8 + r) * 68 + ks * 8 + q + 4];
                mma8(S[nb], qf[ks], bf);
            }
        }

        // online softmax over the two rows this thread owns
        float mx0 = -1e30f, mx1 = -1e30f;
        #pragma unroll
        for (int nb = 0; nb < 8; nb++) {
            mx0 = fmaxf(mx0, fmaxf(S[nb][0], S[nb][1]));
            mx1 = fmaxf(mx1, fmaxf(S[nb][2], S[nb][3]));
        }
        mx0 = fmaxf(mx0, __shfl_xor_sync(0xffffffffu, mx0, 1));
        mx0 = fmaxf(mx0, __shfl_xor_sync(0xffffffffu, mx0, 2));
        mx1 = fmaxf(mx1, __shfl_xor_sync(0xffffffffu, mx1, 1));
        mx1 = fmaxf(mx1, __shfl_xor_sync(0xffffffffu, mx1, 2));
        float mn0 = fmaxf(mrun0, mx0), mn1 = fmaxf(mrun1, mx1);
        float al0 = __expf(mrun0 - mn0), al1 = __expf(mrun1 - mn1);
        float rs0 = 0.f, rs1 = 0.f;
        #pragma unroll
        for (int nb = 0; nb < 8; nb++) {
            S[nb][0] = __expf(S[nb][0] - mn0);
            S[nb][1] = __expf(S[nb][1] - mn0);
            S[nb][2] = __expf(S[nb][2] - mn1);
            S[nb][3] = __expf(S[nb][3] - mn1);
            rs0 += S[nb][0] + S[nb][1];
            rs1 += S[nb][2] + S[nb][3];
        }
        rs0 += __shfl_xor_sync(0xffffffffu, rs0, 1);
        rs0 += __shfl_xor_sync(0xffffffffu, rs0, 2);
        rs1 += __shfl_xor_sync(0xffffffffu, rs1, 1);
        rs1 += __shfl_xor_sync(0xffffffffu, rs1, 2);
        lrun0 = lrun0 * al0 + rs0;
        lrun1 = lrun1 * al1 + rs1;
        mrun0 = mn0; mrun1 = mn1;
        #pragma unroll
        for (int nb = 0; nb < 8; nb++) {
            O[nb][0] *= al0; O[nb][1] *= al0;
            O[nb][2] *= al1; O[nb][3] *= al1;
        }

        __syncthreads();   // everyone done reading Ksm before we overwrite with P
        #pragma unroll
        for (int nb = 0; nb < 8; nb++) {
            Psm[r * 68 + nb * 8 + 2 * q]           = f2tf(S[nb][0]);
            Psm[r * 68 + nb * 8 + 2 * q + 1]       = f2tf(S[nb][1]);
            Psm[(r + 8) * 68 + nb * 8 + 2 * q]     = f2tf(S[nb][2]);
            Psm[(r + 8) * 68 + nb * 8 + 2 * q + 1] = f2tf(S[nb][3]);
        }
        __syncwarp();

        // O += P V
        #pragma unroll
        for (int ks = 0; ks < 8; ks++) {
            unsigned a[4];
            a[0] = Psm[r * 68 + ks * 8 + q];
            a[1] = Psm[(r + 8) * 68 + ks * 8 + q];
            a[2] = Psm[r * 68 + ks * 8 + q + 4];
            a[3] = Psm[(r + 8) * 68 + ks * 8 + q + 4];
            #pragma unroll
            for (int nb = 0; nb < 8; nb++) {
                unsigned bf[2];
                bf[0] = Vsm[(ks * 8 + q) * 72 + nb * 8 + r];
                bf[1] = Vsm[(ks * 8 + q + 4) * 72 + nb * 8 + r];
                mma8(O[nb], a, bf);
            }
        }
        __syncthreads();   // done with Vsm/Psm before next tile load
    }

    float inv0 = 1.f / lrun0;
    float inv1 = 1.f / lrun1;
    float* Og = g_attn + ((size_t)b << 10) * 512;
    #pragma unroll
    for (int nb = 0; nb < 8; nb++) {
        int col = h * 64 + nb * 8 + 2 * q;
        *(float2*)&Og[(size_t)rowA * 512 + col] =
            make_float2(O[nb][0] * inv0, O[nb][1] * inv0);
        *(float2*)&Og[(size_t)(rowA + 8) * 512 + col] =
            make_float2(O[nb][2] * inv1, O[nb][3] * inv1);
    }
}

// ---------------- launch ----------------
extern "C" void kernel_launch(void* const* d_in, const int* in_sizes, int n_in,
                              void* d_out, int out_size) {
    const float* x        = (const float*)d_in[0];
    const float* time     = (const float*)d_in[1];
    const float* ab       = (const float*)d_in[2];
    const float* seq_mask = (const float*)d_in[3];
    const float* gamma    = (const float*)d_in[4];
    const float* Wt       = (const float*)d_in[5];
    const float* bt       = (const float*)d_in[6];
    const float* Wq       = (const float*)d_in[7];
    const float* Wkv      = (const float*)d_in[8];
    const float* Wo       = (const float*)d_in[9];
    const float* Wb       = (const float*)d_in[10];
    const float* bb       = (const float*)d_in[11];
    float* out = (float*)d_out;

    film_kernel<<<512, 256>>>(time, Wt, bt);
    ln_film_kernel<<<4096, 128>>>(x, gamma, seq_mask);
    gemm_kernel<0><<<dim3(8, 32), 256>>>(nullptr, Wq, nullptr, seq_mask);
    gemm_kernel<1><<<dim3(16, 32), 256>>>(x, Wkv, nullptr, seq_mask);
    bias_kernel<<<4096, 256>>>(ab, Wb, bb, seq_mask);
    attn_kernel<<<dim3(16, 8, 4), 128>>>();
    gemm_kernel<2><<<dim3(8, 32), 256>>>(nullptr, Wo, out, seq_mask);
}

// round 5
// speedup vs baseline: 1.7026x; 1.4882x over previous
#include <cuda_runtime.h>
#include <cuda_fp16.h>
#include <cstdint>
#include <cstring>

// ---------------- problem constants ----------------
#define Bc   4
#define Nc_  1024
#define Dc   512
#define Hc   8
#define DHc  64
#define TCc  512
#define ABc  16
#define NEGc 1e6f
#define EPSc 1e-5f

// ---------------- device scratch (no allocs allowed) ----------------
__device__ float  g_st[Bc * 2 * Dc];                        // FiLM scale/shift
__device__ __half g_xn_h[Bc * Nc_ * Dc];                    // normed+FiLM input (4MB)
__device__ __half g_q_h[Bc * Hc * Nc_ * DHc];               // q head-major [bh][n][dh] (4MB)
__device__ __half g_k_h[Bc * Hc * Nc_ * DHc];               // k head-major [bh][n][dh] (4MB)
__device__ __half g_vT_h[Bc * Hc * Nc_ * DHc];              // v TRANSPOSED [bh][dh][n] (4MB)
__device__ __half g_attn_h[Bc * Nc_ * Hc * DHc];            // attention out [b][n][512] (4MB)
__device__ __half g_bias_h[(size_t)Bc * Hc * Nc_ * Nc_];    // projected bias+mask fp16 (64MB)

// ---------------- helpers ----------------
__device__ __forceinline__ unsigned packh2(float x, float y) {
    __half2 h = __floats2half2_rn(x, y);
    unsigned u;
    memcpy(&u, &h, 4);
    return u;
}

__device__ __forceinline__ void mma16(float* c, const unsigned* a, const unsigned* b) {
    asm volatile(
        "mma.sync.aligned.m16n8k16.row.col.f32.f16.f16.f32 "
        "{%0,%1,%2,%3},{%4,%5,%6,%7},{%8,%9},{%0,%1,%2,%3};\n"
        : "+f"(c[0]), "+f"(c[1]), "+f"(c[2]), "+f"(c[3])
        : "r"(a[0]), "r"(a[1]), "r"(a[2]), "r"(a[3]), "r"(b[0]), "r"(b[1]));
}

// ---------------- kernel 1: FiLM  t = silu(time) @ Wt^T + bt ----------------
__global__ void film_kernel(const float* __restrict__ time,
                            const float* __restrict__ Wt,
                            const float* __restrict__ bt) {
    int warp = (blockIdx.x * blockDim.x + threadIdx.x) >> 5;
    int lane = threadIdx.x & 31;
    if (warp >= Bc * 2 * Dc) return;
    int b = warp >> 10;
    int j = warp & 1023;
    const float* t = time + b * TCc;
    const float* w = Wt + (size_t)j * TCc;
    float s = 0.f;
    #pragma unroll 4
    for (int c = lane; c < TCc; c += 32) {
        float x = t[c];
        float sl = x / (1.f + expf(-x));
        s += sl * w[c];
    }
    #pragma unroll
    for (int o = 16; o; o >>= 1) s += __shfl_xor_sync(0xffffffffu, s, o);
    if (lane == 0) g_st[b * 1024 + j] = s + bt[j];
}

// ---------------- kernel 2: LayerNorm + FiLM + seq mask -> fp16 ----------------
__global__ void ln_film_kernel(const float* __restrict__ x,
                               const float* __restrict__ gamma,
                               const float* __restrict__ seq_mask) {
    int row = blockIdx.x;          // 0..4095  (b*1024+n)
    int b   = row >> 10;
    int tid = threadIdx.x;         // 128 threads
    const float* xr = x + (size_t)row * Dc;
    float v[4];
    float s = 0.f, sq = 0.f;
    #pragma unroll
    for (int k = 0; k < 4; k++) {
        v[k] = xr[tid + 128 * k];
        s += v[k];
        sq += v[k] * v[k];
    }
    __shared__ float red[8];
    #pragma unroll
    for (int o = 16; o; o >>= 1) {
        s  += __shfl_xor_sync(0xffffffffu, s, o);
        sq += __shfl_xor_sync(0xffffffffu, sq, o);
    }
    int w = tid >> 5;
    if ((tid & 31) == 0) { red[w] = s; red[4 + w] = sq; }
    __syncthreads();
    s  = red[0] + red[1] + red[2] + red[3];
    sq = red[4] + red[5] + red[6] + red[7];
    float mu  = s * (1.f / 512.f);
    float var = sq * (1.f / 512.f) - mu * mu;
    float inv = rsqrtf(var + EPSc);
    float mask = seq_mask[row];
    __half* o = g_xn_h + (size_t)row * Dc;
    #pragma unroll
    for (int k = 0; k < 4; k++) {
        int d = tid + 128 * k;
        float scale = g_st[b * 1024 + d];
        float shift = g_st[b * 1024 + 512 + d];
        float xn = (v[k] - mu) * inv * gamma[d];
        xn = xn * (scale + 1.f) + shift;
        o[d] = __float2half(xn * mask);
    }
}

// ---------------- fp16 GEMM: 128x64 tile, 256 threads ----------------
// C[M,NC] = A[M,512] * B[NC,512]^T
// MODE 0: A=g_xn_h (half),  out = q*DH^-0.5 -> g_q_h
// MODE 1: A=x (float),      out cols<512 -> g_k_h, cols>=512 -> g_vT_h (transposed)
// MODE 2: A=g_attn_h (half),out -> d_out (float) * seq_mask
template <int MODE>
__global__ void __launch_bounds__(256)
gemm_kernel(const float* __restrict__ Ain,
            const float* __restrict__ Bw,
            float* __restrict__ Out,
            const float* __restrict__ seq_mask) {
    __shared__ __align__(16) __half As[128 * 40];
    __shared__ __align__(16) __half Bs[64 * 40];

    const int m0 = blockIdx.y * 128;
    const int n0 = blockIdx.x * 64;
    const int tid = threadIdx.x;
    const int w = tid >> 5, lane = tid & 31;
    const int wm = w & 3, wn = w >> 2;
    const int r = lane >> 2, q = lane & 3;

    const __half* Ah = (MODE == 0) ? g_xn_h : g_attn_h;

    float C[2][4][4];
    #pragma unroll
    for (int mb = 0; mb < 2; mb++)
        #pragma unroll
        for (int nb = 0; nb < 4; nb++)
            #pragma unroll
            for (int e = 0; e < 4; e++) C[mb][nb][e] = 0.f;

    // prefetch registers
    float4 raf[4]; uint2 rah[4]; float4 rbf[2];
    #pragma unroll
    for (int l = 0; l < 4; l++) {
        int f = l * 256 + tid;
        int row = f >> 3, c4 = (f & 7) * 4;
        if (MODE == 1)
            raf[l] = *(const float4*)&Ain[(size_t)(m0 + row) * 512 + c4];
        else
            rah[l] = *(const uint2*)&Ah[(size_t)(m0 + row) * 512 + c4];
    }
    #pragma unroll
    for (int l = 0; l < 2; l++) {
        int f = l * 256 + tid;
        int row = f >> 3, c4 = (f & 7) * 4;
        rbf[l] = *(const float4*)&Bw[(size_t)(n0 + row) * 512 + c4];
    }

    for (int kc = 0; kc < 512; kc += 32) {
        // stage current chunk
        #pragma unroll
        for (int l = 0; l < 4; l++) {
            int f = l * 256 + tid;
            int row = f >> 3, c4 = (f & 7) * 4;
            if (MODE == 1) {
                uint2 p;
                p.x = packh2(raf[l].x, raf[l].y);
                p.y = packh2(raf[l].z, raf[l].w);
                *(uint2*)&As[row * 40 + c4] = p;
            } else {
                *(uint2*)&As[row * 40 + c4] = rah[l];
            }
        }
        #pragma unroll
        for (int l = 0; l < 2; l++) {
            int f = l * 256 + tid;
            int row = f >> 3, c4 = (f & 7) * 4;
            uint2 p;
            p.x = packh2(rbf[l].x, rbf[l].y);
            p.y = packh2(rbf[l].z, rbf[l].w);
            *(uint2*)&Bs[row * 40 + c4] = p;
        }
        __syncthreads();

        // prefetch next chunk
        if (kc + 32 < 512) {
            #pragma unroll
            for (int l = 0; l < 4; l++) {
                int f = l * 256 + tid;
                int row = f >> 3, c4 = (f & 7) * 4;
                if (MODE == 1)
                    raf[l] = *(const float4*)&Ain[(size_t)(m0 + row) * 512 + kc + 32 + c4];
                else
                    rah[l] = *(const uint2*)&Ah[(size_t)(m0 + row) * 512 + kc + 32 + c4];
            }
            #pragma unroll
            for (int l = 0; l < 2; l++) {
                int f = l * 256 + tid;
                int row = f >> 3, c4 = (f & 7) * 4;
                rbf[l] = *(const float4*)&Bw[(size_t)(n0 + row) * 512 + kc + 32 + c4];
            }
        }

        #pragma unroll
        for (int ks = 0; ks < 2; ks++) {          // two k16 steps per 32-chunk
            unsigned a[2][4], b[4][2];
            #pragma unroll
            for (int mb = 0; mb < 2; mb++) {
                int rr = wm * 32 + mb * 16 + r;
                a[mb][0] = *(const unsigned*)&As[rr * 40 + ks * 16 + 2 * q];
                a[mb][1] = *(const unsigned*)&As[(rr + 8) * 40 + ks * 16 + 2 * q];
                a[mb][2] = *(const unsigned*)&As[rr * 40 + ks * 16 + 2 * q + 8];
                a[mb][3] = *(const unsigned*)&As[(rr + 8) * 40 + ks * 16 + 2 * q + 8];
            }
            #pragma unroll
            for (int nb = 0; nb < 4; nb++) {
                int nr = wn * 32 + nb * 8 + r;
                b[nb][0] = *(const unsigned*)&Bs[nr * 40 + ks * 16 + 2 * q];
                b[nb][1] = *(const unsigned*)&Bs[nr * 40 + ks * 16 + 2 * q + 8];
            }
            #pragma unroll
            for (int mb = 0; mb < 2; mb++)
                #pragma unroll
                for (int nb = 0; nb < 4; nb++)
                    mma16(C[mb][nb], a[mb], b[nb]);
        }
        __syncthreads();
    }

    // epilogue
    #pragma unroll
    for (int mb = 0; mb < 2; mb++) {
        #pragma unroll
        for (int nb = 0; nb < 4; nb++) {
            #pragma unroll
            for (int e = 0; e < 4; e += 2) {
                int row = m0 + wm * 32 + mb * 16 + r + (e ? 8 : 0);
                int col = n0 + wn * 32 + nb * 8 + 2 * q;
                float vx = C[mb][nb][e], vy = C[mb][nb][e + 1];
                if (MODE == 0) {
                    vx *= 0.125f; vy *= 0.125f;    // DH^-0.5
                    int bb_ = row >> 10, n = row & 1023;
                    int h = col >> 6, dh = col & 63;
                    *(unsigned*)&g_q_h[(((size_t)(bb_ * 8 + h)) << 16) + (n << 6) + dh] =
                        packh2(vx, vy);
                } else if (MODE == 1) {
                    int bb_ = row >> 10, n = row & 1023;
                    if (col < 512) {
                        int h = col >> 6, dh = col & 63;
                        *(unsigned*)&g_k_h[(((size_t)(bb_ * 8 + h)) << 16) + (n << 6) + dh] =
                            packh2(vx, vy);
                    } else {
                        int c2 = col - 512;
                        int h = c2 >> 6, dh = c2 & 63;
                        __half* base = g_vT_h + (((size_t)(bb_ * 8 + h)) << 16);
                        base[(dh << 10) + n]       = __float2half(vx);
                        base[((dh + 1) << 10) + n] = __float2half(vy);
                    }
                } else {
                    float mk = seq_mask[row];
                    *(float2*)&Out[(size_t)row * 512 + col] =
                        make_float2(vx * mk, vy * mk);
                }
            }
        }
    }
}

// ---------------- bias projection + mask fold -> fp16 ----------------
__global__ void bias_kernel(const float* __restrict__ ab,
                            const float* __restrict__ Wb,
                            const float* __restrict__ bb,
                            const float* __restrict__ seq_mask) {
    __shared__ float wbs[136];
    int tid = threadIdx.x;
    if (tid < 128) wbs[tid] = Wb[tid];
    if (tid < 8)   wbs[128 + tid] = bb[tid];
    __syncthreads();

    long idx = (long)blockIdx.x * 256 + tid;
    int j4 = (int)(idx & 255);
    int i  = (int)((idx >> 8) & 1023);
    int b  = (int)(idx >> 18);
    int j0 = j4 * 4;

    const float* base = ab + (((long)(b * 16)) << 20) + ((long)i << 10) + j0;
    float4 acc[8];
    #pragma unroll
    for (int h = 0; h < 8; h++) acc[h] = make_float4(0.f, 0.f, 0.f, 0.f);

    #pragma unroll
    for (int a = 0; a < 16; a++) {
        float4 v = *(const float4*)(base + ((long)a << 20));
        #pragma unroll
        for (int h = 0; h < 8; h++) {
            float wv = wbs[h * 16 + a];
            acc[h].x += wv * v.x;
            acc[h].y += wv * v.y;
            acc[h].z += wv * v.z;
            acc[h].w += wv * v.w;
        }
    }
    float mi = seq_mask[b * 1024 + i];
    float4 mj = *(const float4*)&seq_mask[b * 1024 + j0];
    float4 pen;
    pen.x = -(1.f - mi * mj.x) * NEGc;
    pen.y = -(1.f - mi * mj.y) * NEGc;
    pen.z = -(1.f - mi * mj.z) * NEGc;
    pen.w = -(1.f - mi * mj.w) * NEGc;
    #pragma unroll
    for (int h = 0; h < 8; h++) {
        float bbv = wbs[128 + h];
        float ox = fmaxf(acc[h].x + bbv + pen.x, -60000.f);
        float oy = fmaxf(acc[h].y + bbv + pen.y, -60000.f);
        float oz = fmaxf(acc[h].z + bbv + pen.z, -60000.f);
        float ow = fmaxf(acc[h].w + bbv + pen.w, -60000.f);
        __half* dst = &g_bias_h[(((long)(b * 8 + h)) << 20) + ((long)i << 10) + j0];
        uint2 p;
        p.x = packh2(ox, oy);
        p.y = packh2(oz, ow);
        *(uint2*)dst = p;
    }
}

// ---------------- flash attention: (b,h, 128-row q tile), 256 threads ----------------
__global__ void __launch_bounds__(256) attn_kernel() {
    __shared__ __align__(16) __half Ksm[64 * 72];
    __shared__ __align__(16) __half VsmT[64 * 72];

    const int i0 = blockIdx.x * 128;
    const int h  = blockIdx.y;
    const int b  = blockIdx.z;
    const int bh = b * 8 + h;
    const int tid = threadIdx.x, w = tid >> 5, lane = tid & 31;
    const int r = lane >> 2, q = lane & 3;

    const __half* Qh  = g_q_h  + ((size_t)bh << 16);
    const __half* Kgh = g_k_h  + ((size_t)bh << 16);
    const __half* VTh = g_vT_h + ((size_t)bh << 16);
    const __half* Bb  = g_bias_h + ((long)bh << 20);

    const int rowA = i0 + w * 16 + r;     // this thread's first q-row

    // Q fragments: 4 k16 steps
    unsigned qa[4][4];
    #pragma unroll
    for (int ks = 0; ks < 4; ks++) {
        qa[ks][0] = *(const unsigned*)&Qh[(size_t)rowA * 64 + ks * 16 + 2 * q];
        qa[ks][1] = *(const unsigned*)&Qh[(size_t)(rowA + 8) * 64 + ks * 16 + 2 * q];
        qa[ks][2] = *(const unsigned*)&Qh[(size_t)rowA * 64 + ks * 16 + 2 * q + 8];
        qa[ks][3] = *(const unsigned*)&Qh[(size_t)(rowA + 8) * 64 + ks * 16 + 2 * q + 8];
    }

    float O[8][4];
    #pragma unroll
    for (int nb = 0; nb < 8; nb++)
        #pragma unroll
        for (int e = 0; e < 4; e++) O[nb][e] = 0.f;
    float mrun0 = -1e30f, mrun1 = -1e30f;
    float lrun0 = 0.f, lrun1 = 0.f;

    for (int jt = 0; jt < 16; jt++) {
        int j0 = jt * 64;
        // stage K tile [j][dh] and V^T tile [dh][j] (half, direct copy)
        #pragma unroll
        for (int l = 0; l < 4; l++) {
            int f = l * 256 + tid;                // 0..1023
            int row = f >> 4, c4 = (f & 15) * 4;
            *(uint2*)&Ksm[row * 72 + c4] =
                *(const uint2*)&Kgh[(size_t)(j0 + row) * 64 + c4];
            *(uint2*)&VsmT[row * 72 + c4] =
                *(const uint2*)&VTh[((size_t)row << 10) + j0 + c4];
        }
        __syncthreads();

        // S accumulators pre-loaded with bias (+mask penalty folded)
        float S[8][4];
        #pragma unroll
        for (int nb = 0; nb < 8; nb++) {
            int col = j0 + nb * 8 + 2 * q;
            __half2 b01 = *(const __half2*)&Bb[(long)rowA * 1024 + col];
            __half2 b23 = *(const __half2*)&Bb[(long)(rowA + 8) * 1024 + col];
            float2 f01 = __half22float2(b01);
            float2 f23 = __half22float2(b23);
            S[nb][0] = f01.x; S[nb][1] = f01.y;
            S[nb][2] = f23.x; S[nb][3] = f23.y;
        }
        // S += Q K^T   (4 k16 steps x 8 nb)
        #pragma unroll
        for (int ks = 0; ks < 4; ks++) {
            #pragma unroll
            for (int nb = 0; nb < 8; nb++) {
                int nr = nb * 8 + r;
                unsigned bf[2];
                bf[0] = *(const unsigned*)&Ksm[nr * 72 + ks * 16 + 2 * q];
                bf[1] = *(const unsigned*)&Ksm[nr * 72 + ks * 16 + 2 * q + 8];
                mma16(S[nb], qa[ks], bf);
            }
        }

        // online softmax over the two rows this thread owns
        float mx0 = -1e30f, mx1 = -1e30f;
        #pragma unroll
        for (int nb = 0; nb < 8; nb++) {
            mx0 = fmaxf(mx0, fmaxf(S[nb][0], S[nb][1]));
            mx1 = fmaxf(mx1, fmaxf(S[nb][2], S[nb][3]));
        }
        mx0 = fmaxf(mx0, __shfl_xor_sync(0xffffffffu, mx0, 1));
        mx0 = fmaxf(mx0, __shfl_xor_sync(0xffffffffu, mx0, 2));
        mx1 = fmaxf(mx1, __shfl_xor_sync(0xffffffffu, mx1, 1));
        mx1 = fmaxf(mx1, __shfl_xor_sync(0xffffffffu, mx1, 2));
        float mn0 = fmaxf(mrun0, mx0), mn1 = fmaxf(mrun1, mx1);
        float al0 = __expf(mrun0 - mn0), al1 = __expf(mrun1 - mn1);
        float rs0 = 0.f, rs1 = 0.f;
        #pragma unroll
        for (int nb = 0; nb < 8; nb++) {
            S[nb][0] = __expf(S[nb][0] - mn0);
            S[nb][1] = __expf(S[nb][1] - mn0);
            S[nb][2] = __expf(S[nb][2] - mn1);
            S[nb][3] = __expf(S[nb][3] - mn1);
            rs0 += S[nb][0] + S[nb][1];
            rs1 += S[nb][2] + S[nb][3];
        }
        rs0 += __shfl_xor_sync(0xffffffffu, rs0, 1);
        rs0 += __shfl_xor_sync(0xffffffffu, rs0, 2);
        rs1 += __shfl_xor_sync(0xffffffffu, rs1, 1);
        rs1 += __shfl_xor_sync(0xffffffffu, rs1, 2);
        lrun0 = lrun0 * al0 + rs0;
        lrun1 = lrun1 * al1 + rs1;
        mrun0 = mn0; mrun1 = mn1;
        #pragma unroll
        for (int nb = 0; nb < 8; nb++) {
            O[nb][0] *= al0; O[nb][1] *= al0;
            O[nb][2] *= al1; O[nb][3] *= al1;
        }

        // O += P V : P comes straight from registers (C-frag layout == A-frag layout)
        #pragma unroll
        for (int ks = 0; ks < 4; ks++) {
            unsigned pa[4];
            pa[0] = packh2(S[2 * ks][0],     S[2 * ks][1]);
            pa[1] = packh2(S[2 * ks][2],     S[2 * ks][3]);
            pa[2] = packh2(S[2 * ks + 1][0], S[2 * ks + 1][1]);
            pa[3] = packh2(S[2 * ks + 1][2], S[2 * ks + 1][3]);
            #pragma unroll
            for (int nb = 0; nb < 8; nb++) {
                int nr = nb * 8 + r;              // dh index
                unsigned bf[2];
                bf[0] = *(const unsigned*)&VsmT[nr * 72 + ks * 16 + 2 * q];
                bf[1] = *(const unsigned*)&VsmT[nr * 72 + ks * 16 + 2 * q + 8];
                mma16(O[nb], pa, bf);
            }
        }
        __syncthreads();   // done with Ksm/VsmT before next tile staging
    }

    float inv0 = 1.f / lrun0;
    float inv1 = 1.f / lrun1;
    __half* Og = g_attn_h + (((size_t)b << 10)) * 512;
    #pragma unroll
    for (int nb = 0; nb < 8; nb++) {
        int col = h * 64 + nb * 8 + 2 * q;
        *(unsigned*)&Og[(size_t)rowA * 512 + col] =
            packh2(O[nb][0] * inv0, O[nb][1] * inv0);
        *(unsigned*)&Og[(size_t)(rowA + 8) * 512 + col] =
            packh2(O[nb][2] * inv1, O[nb][3] * inv1);
    }
}

// ---------------- launch ----------------
extern "C" void kernel_launch(void* const* d_in, const int* in_sizes, int n_in,
                              void* d_out, int out_size) {
    const float* x        = (const float*)d_in[0];
    const float* time     = (const float*)d_in[1];
    const float* ab       = (const float*)d_in[2];
    const float* seq_mask = (const float*)d_in[3];
    const float* gamma    = (const float*)d_in[4];
    const float* Wt       = (const float*)d_in[5];
    const float* bt       = (const float*)d_in[6];
    const float* Wq       = (const float*)d_in[7];
    const float* Wkv      = (const float*)d_in[8];
    const float* Wo       = (const float*)d_in[9];
    const float* Wb       = (const float*)d_in[10];
    const float* bb       = (const float*)d_in[11];
    float* out = (float*)d_out;

    film_kernel<<<512, 256>>>(time, Wt, bt);
    ln_film_kernel<<<4096, 128>>>(x, gamma, seq_mask);
    gemm_kernel<0><<<dim3(8, 32), 256>>>(nullptr, Wq, nullptr, seq_mask);
    gemm_kernel<1><<<dim3(16, 32), 256>>>(x, Wkv, nullptr, seq_mask);
    bias_kernel<<<4096, 256>>>(ab, Wb, bb, seq_mask);
    attn_kernel<<<dim3(8, 8, 4), 256>>>();
    gemm_kernel<2><<<dim3(8, 32), 256>>>(nullptr, Wo, out, seq_mask);
}

// round 8
// speedup vs baseline: 2.0069x; 1.1787x over previous
#include <cuda_runtime.h>
#include <cuda_fp16.h>
#include <cstdint>
#include <cstring>

// ---------------- problem constants ----------------
#define Bc   4
#define Nc_  1024
#define Dc   512
#define Hc   8
#define DHc  64
#define TCc  512
#define ABc  16
#define NEGc 1e6f
#define EPSc 1e-5f

// ---------------- device scratch (no allocs allowed) ----------------
__device__ float  g_st[Bc * 2 * Dc];                        // FiLM scale/shift
__device__ __half g_xn_h[Bc * Nc_ * Dc];                    // normed+FiLM input (4MB)
__device__ __half g_x_h[Bc * Nc_ * Dc];                     // raw x fp16 (4MB)
__device__ __half g_q_h[Bc * Hc * Nc_ * DHc];               // q head-major [bh][n][dh]
__device__ __half g_k_h[Bc * Hc * Nc_ * DHc];               // k head-major [bh][n][dh]
__device__ __half g_vT_h[Bc * Hc * Nc_ * DHc];              // v TRANSPOSED [bh][dh][n]
__device__ __half g_attn_h[Bc * Nc_ * Hc * DHc];            // attention out [b][n][512]
__device__ __half g_bias_h[(size_t)Bc * Hc * Nc_ * Nc_];    // projected bias+mask fp16 (64MB)
__device__ __half g_wq_h[512 * 512];                        // fp16 weights
__device__ __half g_wkv_h[1024 * 512];
__device__ __half g_wo_h[512 * 512];

// ---------------- helpers ----------------
__device__ __forceinline__ unsigned packh2(float x, float y) {
    __half2 h = __floats2half2_rn(x, y);
    unsigned u;
    memcpy(&u, &h, 4);
    return u;
}

__device__ __forceinline__ void mma16(float* c, const unsigned* a, const unsigned* b) {
    asm volatile(
        "mma.sync.aligned.m16n8k16.row.col.f32.f16.f16.f32 "
        "{%0,%1,%2,%3},{%4,%5,%6,%7},{%8,%9},{%0,%1,%2,%3};\n"
        : "+f"(c[0]), "+f"(c[1]), "+f"(c[2]), "+f"(c[3])
        : "r"(a[0]), "r"(a[1]), "r"(a[2]), "r"(a[3]), "r"(b[0]), "r"(b[1]));
}

__device__ __forceinline__ void ldsm_x4(unsigned* d, const __half* p) {
    unsigned addr = (unsigned)__cvta_generic_to_shared(p);
    asm volatile("ldmatrix.sync.aligned.m8n8.x4.shared.b16 {%0,%1,%2,%3}, [%4];"
                 : "=r"(d[0]), "=r"(d[1]), "=r"(d[2]), "=r"(d[3]) : "r"(addr));
}

__device__ __forceinline__ void cpasync16(__half* dst, const __half* src) {
    unsigned d = (unsigned)__cvta_generic_to_shared(dst);
    asm volatile("cp.async.cg.shared.global [%0], [%1], 16;" :: "r"(d), "l"(src));
}
#define CP_COMMIT() asm volatile("cp.async.commit_group;")
#define CP_WAIT1()  asm volatile("cp.async.wait_group 1;")

// ---------------- kernel 0: weight fp32->fp16 conversion ----------------
__global__ void wconv_kernel(const float* __restrict__ Wq,
                             const float* __restrict__ Wkv,
                             const float* __restrict__ Wo) {
    int i = blockIdx.x * 256 + threadIdx.x;      // per float4, 262144 total
    const float* src; __half* dst; int off;
    if (i < 65536)            { src = Wq;  dst = g_wq_h;  off = i; }
    else if (i < 196608)      { src = Wkv; dst = g_wkv_h; off = i - 65536; }
    else                      { src = Wo;  dst = g_wo_h;  off = i - 196608; }
    float4 v = ((const float4*)src)[off];
    uint2 p;
    p.x = packh2(v.x, v.y);
    p.y = packh2(v.z, v.w);
    ((uint2*)dst)[off] = p;
}

// ---------------- kernel 1: FiLM  t = silu(time) @ Wt^T + bt ----------------
__global__ void film_kernel(const float* __restrict__ time,
                            const float* __restrict__ Wt,
                            const float* __restrict__ bt) {
    int warp = (blockIdx.x * blockDim.x + threadIdx.x) >> 5;
    int lane = threadIdx.x & 31;
    if (warp >= Bc * 2 * Dc) return;
    int b = warp >> 10;
    int j = warp & 1023;
    const float* t = time + b * TCc;
    const float* w = Wt + (size_t)j * TCc;
    float s = 0.f;
    #pragma unroll 4
    for (int c = lane; c < TCc; c += 32) {
        float x = t[c];
        float sl = x / (1.f + expf(-x));
        s += sl * w[c];
    }
    #pragma unroll
    for (int o = 16; o; o >>= 1) s += __shfl_xor_sync(0xffffffffu, s, o);
    if (lane == 0) g_st[b * 1024 + j] = s + bt[j];
}

// ---------------- kernel 2: LayerNorm + FiLM + mask -> fp16 (also x -> fp16) ----------------
__global__ void ln_film_kernel(const float* __restrict__ x,
                               const float* __restrict__ gamma,
                               const float* __restrict__ seq_mask) {
    int row = blockIdx.x;          // 0..4095
    int b   = row >> 10;
    int tid = threadIdx.x;         // 128 threads
    const float* xr = x + (size_t)row * Dc;
    float v[4];
    float s = 0.f, sq = 0.f;
    #pragma unroll
    for (int k = 0; k < 4; k++) {
        v[k] = xr[tid + 128 * k];
        s += v[k];
        sq += v[k] * v[k];
    }
    __shared__ float red[8];
    #pragma unroll
    for (int o = 16; o; o >>= 1) {
        s  += __shfl_xor_sync(0xffffffffu, s, o);
        sq += __shfl_xor_sync(0xffffffffu, sq, o);
    }
    int w = tid >> 5;
    if ((tid & 31) == 0) { red[w] = s; red[4 + w] = sq; }
    __syncthreads();
    s  = red[0] + red[1] + red[2] + red[3];
    sq = red[4] + red[5] + red[6] + red[7];
    float mu  = s * (1.f / 512.f);
    float var = sq * (1.f / 512.f) - mu * mu;
    float inv = rsqrtf(var + EPSc);
    float mask = seq_mask[row];
    __half* o  = g_xn_h + (size_t)row * Dc;
    __half* ox = g_x_h  + (size_t)row * Dc;
    #pragma unroll
    for (int k = 0; k < 4; k++) {
        int d = tid + 128 * k;
        float scale = g_st[b * 1024 + d];
        float shift = g_st[b * 1024 + 512 + d];
        float xn = (v[k] - mu) * inv * gamma[d];
        xn = xn * (scale + 1.f) + shift;
        o[d]  = __float2half(xn * mask);
        ox[d] = __float2half(v[k]);
    }
}

// ---------------- fp16 GEMM: 128x128 tile, 256 thr, cp.async 2-stage, ldmatrix ----------------
// C[M,NC] = A[M,512] * B[NC,512]^T    (all fp16 operands)
// MODE 0: A=g_xn_h, B=g_wq_h,  out=q*0.125 -> g_q_h
// MODE 1: A=g_x_h,  B=g_wkv_h, cols<512 -> g_k_h, cols>=512 -> g_vT_h (transposed)
// MODE 2: A=g_attn_h,B=g_wo_h, out -> d_out(fp32)*seq_mask
template <int MODE>
__global__ void __launch_bounds__(256, 2)
gemm_kernel(float* __restrict__ Out, const float* __restrict__ seq_mask) {
    __shared__ __align__(16) __half As[2][128 * 40];
    __shared__ __align__(16) __half Bs[2][128 * 40];
    const __half* Ah = (MODE == 0) ? g_xn_h : (MODE == 1 ? g_x_h : g_attn_h);
    const __half* Bh = (MODE == 0) ? g_wq_h : (MODE == 1 ? g_wkv_h : g_wo_h);

    const int m0 = blockIdx.y * 128;
    const int n0 = blockIdx.x * 128;
    const int tid = threadIdx.x;
    const int w = tid >> 5, lane = tid & 31;
    const int wm = w & 1, wn = w >> 1;           // 2 warps M (64 rows), 4 warps N (32 cols)
    const int r = lane >> 2, q = lane & 3;

    float C[4][4][4];
    #pragma unroll
    for (int mb = 0; mb < 4; mb++)
        #pragma unroll
        for (int nb = 0; nb < 4; nb++)
            #pragma unroll
            for (int e = 0; e < 4; e++) C[mb][nb][e] = 0.f;

    // cp.async slot assignment: 512 x 16B per operand per stage, 2 per thread
    const int f0 = tid, f1 = 256 + tid;
    const int ar0 = f0 >> 2, ac0 = (f0 & 3) * 8;
    const int ar1 = f1 >> 2, ac1 = (f1 & 3) * 8;

    // per-lane ldmatrix base offsets (halves)
    const int a_off = (wm * 64 + ((lane >> 3) & 1) * 8 + (lane & 7)) * 40 + (lane >> 4) * 8;
    const int b_off = (wn * 32 + (lane >> 4) * 8 + (lane & 7)) * 40 + ((lane >> 3) & 1) * 8;

    // prologue: stages 0,1
    #pragma unroll
    for (int s = 0; s < 2; s++) {
        int kc = s * 32;
        cpasync16(&As[s][ar0 * 40 + ac0], &Ah[(size_t)(m0 + ar0) * 512 + kc + ac0]);
        cpasync16(&As[s][ar1 * 40 + ac1], &Ah[(size_t)(m0 + ar1) * 512 + kc + ac1]);
        cpasync16(&Bs[s][ar0 * 40 + ac0], &Bh[(size_t)(n0 + ar0) * 512 + kc + ac0]);
        cpasync16(&Bs[s][ar1 * 40 + ac1], &Bh[(size_t)(n0 + ar1) * 512 + kc + ac1]);
        CP_COMMIT();
    }

    for (int it = 0; it < 16; it++) {
        CP_WAIT1();
        __syncthreads();
        const __half* Ab = As[it & 1];
        const __half* Bb = Bs[it & 1];
        #pragma unroll
        for (int ks = 0; ks < 2; ks++) {
            unsigned af[4][4], bf[2][4];
            #pragma unroll
            for (int mb = 0; mb < 4; mb++)
                ldsm_x4(af[mb], Ab + a_off + mb * 16 * 40 + ks * 16);
            #pragma unroll
            for (int ng = 0; ng < 2; ng++)
                ldsm_x4(bf[ng], Bb + b_off + ng * 16 * 40 + ks * 16);
            #pragma unroll
            for (int mb = 0; mb < 4; mb++)
                #pragma unroll
                for (int nb = 0; nb < 4; nb++)
                    mma16(C[mb][nb], af[mb], &bf[nb >> 1][(nb & 1) * 2]);
        }
        __syncthreads();
        if (it + 2 < 16) {
            int s = it & 1, kc = (it + 2) * 32;
            cpasync16(&As[s][ar0 * 40 + ac0], &Ah[(size_t)(m0 + ar0) * 512 + kc + ac0]);
            cpasync16(&As[s][ar1 * 40 + ac1], &Ah[(size_t)(m0 + ar1) * 512 + kc + ac1]);
            cpasync16(&Bs[s][ar0 * 40 + ac0], &Bh[(size_t)(n0 + ar0) * 512 + kc + ac0]);
            cpasync16(&Bs[s][ar1 * 40 + ac1], &Bh[(size_t)(n0 + ar1) * 512 + kc + ac1]);
        }
        CP_COMMIT();
    }

    // epilogue
    #pragma unroll
    for (int mb = 0; mb < 4; mb++) {
        #pragma unroll
        for (int nb = 0; nb < 4; nb++) {
            #pragma unroll
            for (int e = 0; e < 4; e += 2) {
                int row = m0 + wm * 64 + mb * 16 + r + (e ? 8 : 0);
                int col = n0 + wn * 32 + nb * 8 + 2 * q;
                float vx = C[mb][nb][e], vy = C[mb][nb][e + 1];
                if (MODE == 0) {
                    vx *= 0.125f; vy *= 0.125f;
                    int bb_ = row >> 10, n = row & 1023;
                    int h = col >> 6, dh = col & 63;
                    *(unsigned*)&g_q_h[(((size_t)(bb_ * 8 + h)) << 16) + (n << 6) + dh] =
                        packh2(vx, vy);
                } else if (MODE == 1) {
                    int bb_ = row >> 10, n = row & 1023;
                    if (col < 512) {
                        int h = col >> 6, dh = col & 63;
                        *(unsigned*)&g_k_h[(((size_t)(bb_ * 8 + h)) << 16) + (n << 6) + dh] =
                            packh2(vx, vy);
                    } else {
                        int c2 = col - 512;
                        int h = c2 >> 6, dh = c2 & 63;
                        __half* base = g_vT_h + (((size_t)(bb_ * 8 + h)) << 16);
                        base[(dh << 10) + n]       = __float2half(vx);
                        base[((dh + 1) << 10) + n] = __float2half(vy);
                    }
                } else {
                    float mk = seq_mask[row];
                    *(float2*)&Out[(size_t)row * 512 + col] =
                        make_float2(vx * mk, vy * mk);
                }
            }
        }
    }
}

// ---------------- bias projection + mask fold -> fp16 ----------------
__global__ void bias_kernel(const float* __restrict__ ab,
                            const float* __restrict__ Wb,
                            const float* __restrict__ bb,
                            const float* __restrict__ seq_mask) {
    __shared__ float wbs[136];
    int tid = threadIdx.x;
    if (tid < 128) wbs[tid] = Wb[tid];
    if (tid < 8)   wbs[128 + tid] = bb[tid];
    __syncthreads();

    long idx = (long)blockIdx.x * 256 + tid;
    int j4 = (int)(idx & 255);
    int i  = (int)((idx >> 8) & 1023);
    int b  = (int)(idx >> 18);
    int j0 = j4 * 4;

    const float* base = ab + (((long)(b * 16)) << 20) + ((long)i << 10) + j0;
    float4 acc[8];
    #pragma unroll
    for (int h = 0; h < 8; h++) acc[h] = make_float4(0.f, 0.f, 0.f, 0.f);

    #pragma unroll
    for (int a = 0; a < 16; a++) {
        float4 v = *(const float4*)(base + ((long)a << 20));
        #pragma unroll
        for (int h = 0; h < 8; h++) {
            float wv = wbs[h * 16 + a];
            acc[h].x += wv * v.x;
            acc[h].y += wv * v.y;
            acc[h].z += wv * v.z;
            acc[h].w += wv * v.w;
        }
    }
    float mi = seq_mask[b * 1024 + i];
    float4 mj = *(const float4*)&seq_mask[b * 1024 + j0];
    float4 pen;
    pen.x = -(1.f - mi * mj.x) * NEGc;
    pen.y = -(1.f - mi * mj.y) * NEGc;
    pen.z = -(1.f - mi * mj.z) * NEGc;
    pen.w = -(1.f - mi * mj.w) * NEGc;
    #pragma unroll
    for (int h = 0; h < 8; h++) {
        float bbv = wbs[128 + h];
        float ox = fmaxf(acc[h].x + bbv + pen.x, -60000.f);
        float oy = fmaxf(acc[h].y + bbv + pen.y, -60000.f);
        float oz = fmaxf(acc[h].z + bbv + pen.z, -60000.f);
        float ow = fmaxf(acc[h].w + bbv + pen.w, -60000.f);
        __half* dst = &g_bias_h[(((long)(b * 8 + h)) << 20) + ((long)i << 10) + j0];
        uint2 p;
        p.x = packh2(ox, oy);
        p.y = packh2(oz, ow);
        *(uint2*)dst = p;
    }
}

// ---------------- flash attention: (b,h, 128-row q tile), 256 threads ----------------
__global__ void __launch_bounds__(256) attn_kernel() {
    __shared__ __align__(16) __half Ksm[64 * 72];
    __shared__ __align__(16) __half VsmT[64 * 72];

    const int i0 = blockIdx.x * 128;
    const int h  = blockIdx.y;
    const int b  = blockIdx.z;
    const int bh = b * 8 + h;
    const int tid = threadIdx.x, w = tid >> 5, lane = tid & 31;
    const int r = lane >> 2, q = lane & 3;

    const __half* Qh  = g_q_h  + ((size_t)bh << 16);
    const __half* Kgh = g_k_h  + ((size_t)bh << 16);
    const __half* VTh = g_vT_h + ((size_t)bh << 16);
    const __half* Bb  = g_bias_h + ((long)bh << 20);

    const int rowA = i0 + w * 16 + r;

    // per-lane ldmatrix base offset for Ksm/VsmT (stride 72)
    const int kb_off = ((lane >> 4) * 8 + (lane & 7)) * 72 + ((lane >> 3) & 1) * 8;

    unsigned qa[4][4];
    #pragma unroll
    for (int ks = 0; ks < 4; ks++) {
        qa[ks][0] = *(const unsigned*)&Qh[(size_t)rowA * 64 + ks * 16 + 2 * q];
        qa[ks][1] = *(const unsigned*)&Qh[(size_t)(rowA + 8) * 64 + ks * 16 + 2 * q];
        qa[ks][2] = *(const unsigned*)&Qh[(size_t)rowA * 64 + ks * 16 + 2 * q + 8];
        qa[ks][3] = *(const unsigned*)&Qh[(size_t)(rowA + 8) * 64 + ks * 16 + 2 * q + 8];
    }

    float O[8][4];
    #pragma unroll
    for (int nb = 0; nb < 8; nb++)
        #pragma unroll
        for (int e = 0; e < 4; e++) O[nb][e] = 0.f;
    float mrun0 = -1e30f, mrun1 = -1e30f;
    float lrun0 = 0.f, lrun1 = 0.f;

    for (int jt = 0; jt < 16; jt++) {
        int j0 = jt * 64;
        #pragma unroll
        for (int l = 0; l < 4; l++) {
            int f = l * 256 + tid;
            int row = f >> 4, c4 = (f & 15) * 4;
            *(uint2*)&Ksm[row * 72 + c4] =
                *(const uint2*)&Kgh[(size_t)(j0 + row) * 64 + c4];
            *(uint2*)&VsmT[row * 72 + c4] =
                *(const uint2*)&VTh[((size_t)row << 10) + j0 + c4];
        }
        __syncthreads();

        // S pre-loaded with bias(+mask)
        float S[8][4];
        #pragma unroll
        for (int nb = 0; nb < 8; nb++) {
            int col = j0 + nb * 8 + 2 * q;
            float2 f01 = __half22float2(*(const __half2*)&Bb[(long)rowA * 1024 + col]);
            float2 f23 = __half22float2(*(const __half2*)&Bb[(long)(rowA + 8) * 1024 + col]);
            S[nb][0] = f01.x; S[nb][1] = f01.y;
            S[nb][2] = f23.x; S[nb][3] = f23.y;
        }
        // S += Q K^T
        #pragma unroll
        for (int ks = 0; ks < 4; ks++) {
            unsigned bf[4][4];
            #pragma unroll
            for (int ng = 0; ng < 4; ng++)
                ldsm_x4(bf[ng], Ksm + kb_off + ng * 16 * 72 + ks * 16);
            #pragma unroll
            for (int nb = 0; nb < 8; nb++)
                mma16(S[nb], qa[ks], &bf[nb >> 1][(nb & 1) * 2]);
        }

        // online softmax (two rows per thread)
        float mx0 = -1e30f, mx1 = -1e30f;
        #pragma unroll
        for (int nb = 0; nb < 8; nb++) {
            mx0 = fmaxf(mx0, fmaxf(S[nb][0], S[nb][1]));
            mx1 = fmaxf(mx1, fmaxf(S[nb][2], S[nb][3]));
        }
        mx0 = fmaxf(mx0, __shfl_xor_sync(0xffffffffu, mx0, 1));
        mx0 = fmaxf(mx0, __shfl_xor_sync(0xffffffffu, mx0, 2));
        mx1 = fmaxf(mx1, __shfl_xor_sync(0xffffffffu, mx1, 1));
        mx1 = fmaxf(mx1, __shfl_xor_sync(0xffffffffu, mx1, 2));
        float mn0 = fmaxf(mrun0, mx0), mn1 = fmaxf(mrun1, mx1);
        float al0 = __expf(mrun0 - mn0), al1 = __expf(mrun1 - mn1);
        float rs0 = 0.f, rs1 = 0.f;
        #pragma unroll
        for (int nb = 0; nb < 8; nb++) {
            S[nb][0] = __expf(S[nb][0] - mn0);
            S[nb][1] = __expf(S[nb][1] - mn0);
            S[nb][2] = __expf(S[nb][2] - mn1);
            S[nb][3] = __expf(S[nb][3] - mn1);
            rs0 += S[nb][0] + S[nb][1];
            rs1 += S[nb][2] + S[nb][3];
        }
        rs0 += __shfl_xor_sync(0xffffffffu, rs0, 1);
        rs0 += __shfl_xor_sync(0xffffffffu, rs0, 2);
        rs1 += __shfl_xor_sync(0xffffffffu, rs1, 1);
        rs1 += __shfl_xor_sync(0xffffffffu, rs1, 2);
        lrun0 = lrun0 * al0 + rs0;
        lrun1 = lrun1 * al1 + rs1;
        mrun0 = mn0; mrun1 = mn1;
        #pragma unroll
        for (int nb = 0; nb < 8; nb++) {
            O[nb][0] *= al0; O[nb][1] *= al0;
            O[nb][2] *= al1; O[nb][3] *= al1;
        }

        // O += P V  (P straight from registers)
        #pragma unroll
        for (int ks = 0; ks < 4; ks++) {
            unsigned pa[4];
            pa[0] = packh2(S[2 * ks][0],     S[2 * ks][1]);
            pa[1] = packh2(S[2 * ks][2],     S[2 * ks][3]);
            pa[2] = packh2(S[2 * ks + 1][0], S[2 * ks + 1][1]);
            pa[3] = packh2(S[2 * ks + 1][2], S[2 * ks + 1][3]);
            unsigned bf[4][4];
            #pragma unroll
            for (int ng = 0; ng < 4; ng++)
                ldsm_x4(bf[ng], VsmT + kb_off + ng * 16 * 72 + ks * 16);
            #pragma unroll
            for (int nb = 0; nb < 8; nb++)
                mma16(O[nb], pa, &bf[nb >> 1][(nb & 1) * 2]);
        }
        __syncthreads();
    }

    float inv0 = 1.f / lrun0;
    float inv1 = 1.f / lrun1;
    __half* Og = g_attn_h + (((size_t)b << 10)) * 512;
    #pragma unroll
    for (int nb = 0; nb < 8; nb++) {
        int col = h * 64 + nb * 8 + 2 * q;
        *(unsigned*)&Og[(size_t)rowA * 512 + col] =
            packh2(O[nb][0] * inv0, O[nb][1] * inv0);
        *(unsigned*)&Og[(size_t)(rowA + 8) * 512 + col] =
            packh2(O[nb][2] * inv1, O[nb][3] * inv1);
    }
}

// ---------------- launch ----------------
extern "C" void kernel_launch(void* const* d_in, const int* in_sizes, int n_in,
                              void* d_out, int out_size) {
    const float* x        = (const float*)d_in[0];
    const float* time     = (const float*)d_in[1];
    const float* ab       = (const float*)d_in[2];
    const float* seq_mask = (const float*)d_in[3];
    const float* gamma    = (const float*)d_in[4];
    const float* Wt       = (const float*)d_in[5];
    const float* bt       = (const float*)d_in[6];
    const float* Wq       = (const float*)d_in[7];
    const float* Wkv      = (const float*)d_in[8];
    const float* Wo       = (const float*)d_in[9];
    const float* Wb       = (const float*)d_in[10];
    const float* bb       = (const float*)d_in[11];
    float* out = (float*)d_out;

    wconv_kernel<<<1024, 256>>>(Wq, Wkv, Wo);
    film_kernel<<<512, 256>>>(time, Wt, bt);
    ln_film_kernel<<<4096, 128>>>(x, gamma, seq_mask);
    gemm_kernel<0><<<dim3(4, 32), 256>>>(nullptr, seq_mask);
    gemm_kernel<1><<<dim3(8, 32), 256>>>(nullptr, seq_mask);
    bias_kernel<<<4096, 256>>>(ab, Wb, bb, seq_mask);
    attn_kernel<<<dim3(8, 8, 4), 256>>>();
    gemm_kernel<2><<<dim3(4, 32), 256>>>(out, seq_mask);
}